// round 7
// baseline (speedup 1.0000x reference)
#include <cuda_runtime.h>
#include <cstdint>

// ---------------------------------------------------------------------------
// Seq2seq BiLSTM (encoder 336 steps + autoregressive decoder 24 iters)
// Persistent cooperative kernel, fp32 FFMA, flag-array grid barrier.
//
// Grid = 128 CTAs = 2 dirs x 4 batch-tiles(32) x 16 j-tiles(16).
// 256 threads/CTA (2 warps per SMSP for latency hiding).
// Each thread owns 2 batch rows x 4 gates of one hidden unit j:
//   - c state in registers for the whole run
//   - weights in SMEM, layout [k][j*4+gate] -> LDS.128 per k for all gates
//   - h published to global each round; grid barrier between rounds
// ---------------------------------------------------------------------------

#define NBLK 128
#define NTHR 256

namespace {
constexpr int BATCH = 128;
constexpr int SEQLEN = 336;
constexpr int PRED = 24;
constexpr int IN = 64;
constexpr int HID = 256;
constexpr int KTOT = IN + HID;          // 320
constexpr int WS = 68;                  // W smem row stride (floats): 68*4=272B, 16B-aligned
constexpr int AS = 328;                 // A smem row stride (floats): 1312B, 16B-aligned
constexpr int SMEM_FLOATS = KTOT * WS + 32 * AS + 64 + NTHR;
constexpr int SMEM_BYTES = SMEM_FLOATS * 4;
}

// Persistent device state
__device__ float g_h[2 * BATCH * HID];          // hidden states, both dirs
__device__ float g_y[PRED * BATCH * IN];        // decoder outputs (autoregressive feed)
__device__ int   g_flags[NBLK];                 // grid barrier flags

__device__ __forceinline__ float sigmoidf_(float x) {
    return 1.0f / (1.0f + __expf(-x));
}

// Flat grid barrier: each CTA publishes its round; each thread polls one flag.
__device__ __forceinline__ void gridbar(int round) {
    __threadfence();
    __syncthreads();
    if (threadIdx.x == 0)
        ((volatile int*)g_flags)[blockIdx.x] = round;
    volatile int* f = (volatile int*)g_flags;
    const int pi = threadIdx.x & (NBLK - 1);
    if (f[pi] < round) {
        while (f[pi] < round) { __nanosleep(32); }
    }
    __syncthreads();
    __threadfence();
}

// Stage per-phase weight slice into SMEM:
//   Wsm[k*WS + c],  c = jj*4 + g  (jj = hidden unit within j-tile, g = gate)
//   source row = g*256 + j0 + jj;  k<64 -> Wih, else Whh.
//   bsum[c] = bih + bhh.
__device__ void load_phase_weights(float* Wsm, float* bsum,
                                   const float* __restrict__ Wih,
                                   const float* __restrict__ Whh,
                                   const float* __restrict__ bih,
                                   const float* __restrict__ bhh,
                                   int d, int j0) {
    for (int idx = threadIdx.x; idx < 64 * KTOT; idx += NTHR) {
        int c = idx / KTOT;
        int k = idx - c * KTOT;
        int jj = c >> 2, g = c & 3;
        int row = g * 256 + j0 + jj;
        float v = (k < IN) ? Wih[(d * 1024 + row) * IN + k]
                           : Whh[(d * 1024 + row) * HID + (k - IN)];
        Wsm[k * WS + c] = v;
    }
    for (int c = threadIdx.x; c < 64; c += NTHR) {
        int jj = c >> 2, g = c & 3;
        int row = g * 256 + j0 + jj;
        bsum[c] = bih[d * 1024 + row] + bhh[d * 1024 + row];
    }
}

// One LSTM cell step for this CTA's slice.
__device__ void cell_round(const float* __restrict__ src, int rowStride,
                           int d, int b0, int j0,
                           const float* Wsm, float* Asm, const float* bsum,
                           float c_reg[2]) {
    const int tid = threadIdx.x;

    // ---- stage A = [x_t | h] tile: 32 rows x 320 floats (80 float4/row)
#pragma unroll
    for (int it = 0; it < (32 * 80) / NTHR; it++) {
        int idx = tid + it * NTHR;
        int row = idx / 80;
        int slot = idx - row * 80;
        int b = b0 + row;
        float4 v;
        if (slot < 16)
            v = __ldcg((const float4*)(src + (size_t)b * rowStride) + slot);
        else
            v = __ldcg((const float4*)(g_h + ((d << 7) + b) * HID) + (slot - 16));
        *(float4*)(Asm + row * AS + slot * 4) = v;
    }
    __syncthreads();

    // ---- GEMM: thread = 2 batch rows x 4 gates of one hidden unit (tj)
    const int tj = tid & 15;
    const int tb = tid >> 4;       // 0..15, 2 batch rows each
    float acc[2][4];
    {
        float4 bv = *(const float4*)(bsum + tj * 4);
        acc[0][0] = bv.x; acc[0][1] = bv.y; acc[0][2] = bv.z; acc[0][3] = bv.w;
        acc[1][0] = bv.x; acc[1][1] = bv.y; acc[1][2] = bv.z; acc[1][3] = bv.w;
    }

    const float* A0 = Asm + (tb * 2 + 0) * AS;
    const float* A1 = A0 + AS;
    const float* Wp = Wsm + tj * 4;

#pragma unroll 4
    for (int k = 0; k < KTOT; k += 4) {
        float4 a0 = *(const float4*)(A0 + k);
        float4 a1 = *(const float4*)(A1 + k);
        float a0v[4] = {a0.x, a0.y, a0.z, a0.w};
        float a1v[4] = {a1.x, a1.y, a1.z, a1.w};
#pragma unroll
        for (int kk = 0; kk < 4; kk++) {
            float4 w = *(const float4*)(Wp + (k + kk) * WS);
            acc[0][0] = fmaf(a0v[kk], w.x, acc[0][0]);
            acc[0][1] = fmaf(a0v[kk], w.y, acc[0][1]);
            acc[0][2] = fmaf(a0v[kk], w.z, acc[0][2]);
            acc[0][3] = fmaf(a0v[kk], w.w, acc[0][3]);
            acc[1][0] = fmaf(a1v[kk], w.x, acc[1][0]);
            acc[1][1] = fmaf(a1v[kk], w.y, acc[1][1]);
            acc[1][2] = fmaf(a1v[kk], w.z, acc[1][2]);
            acc[1][3] = fmaf(a1v[kk], w.w, acc[1][3]);
        }
    }

    // ---- pointwise LSTM update (c stays in registers), publish h
    int j = j0 + tj;
#pragma unroll
    for (int bi = 0; bi < 2; bi++) {
        int b = b0 + tb * 2 + bi;
        float gi = acc[bi][0], gf = acc[bi][1], gg = acc[bi][2], go = acc[bi][3];
        float cn = sigmoidf_(gf) * c_reg[bi] + sigmoidf_(gi) * tanhf(gg);
        float hn = sigmoidf_(go) * tanhf(cn);
        c_reg[bi] = cn;
        g_h[((d << 7) + b) * HID + j] = hn;
    }
}

__global__ void __launch_bounds__(NTHR, 1)
lstm_s2s_kernel(const float* __restrict__ x,
                const float* __restrict__ eWih, const float* __restrict__ eWhh,
                const float* __restrict__ ebih, const float* __restrict__ ebhh,
                const float* __restrict__ dWih, const float* __restrict__ dWhh,
                const float* __restrict__ dbih, const float* __restrict__ dbhh,
                const float* __restrict__ linW, const float* __restrict__ linb,
                float* __restrict__ out) {
    extern __shared__ float smem[];
    float* Wsm  = smem;                        // [320][68]
    float* Asm  = Wsm + KTOT * WS;             // [32][328]
    float* bsum = Asm + 32 * AS;               // [64]
    float* red  = bsum + 64;                   // [256] projection scratch

    const int ct = blockIdx.x;
    const int d = ct >> 6;
    const int rem = ct & 63;
    const int b0 = (rem >> 4) * 32;
    const int j0 = (rem & 15) * 16;
    const int tid = threadIdx.x;

    int round = 0;
    float c_reg[2] = {0.f, 0.f};

    // zero this CTA's h slice (fresh state every launch/replay)
    for (int idx = tid; idx < 32 * 16; idx += NTHR) {
        int bb = idx >> 4, jj = idx & 15;
        g_h[((d << 7) + b0 + bb) * HID + j0 + jj] = 0.f;
    }

    load_phase_weights(Wsm, bsum, eWih, eWhh, ebih, ebhh, d, j0);
    gridbar(++round);

    // ===== encoder: 336 rounds, fwd & bwd dirs in parallel across CTAs =====
    for (int r = 0; r < SEQLEN; r++) {
        int t = (d == 0) ? r : (SEQLEN - 1 - r);
        cell_round(x + t * IN, SEQLEN * IN, d, b0, j0, Wsm, Asm, bsum, c_reg);
        gridbar(++round);
    }

    // switch to decoder weights (next cell_round's __syncthreads orders this)
    load_phase_weights(Wsm, bsum, dWih, dWhh, dbih, dbhh, d, j0);

    // ===== decoder: 24 autoregressive iterations =====
    for (int t = 0; t < PRED; t++) {
        int L = (t == 0) ? 1 : t;
        for (int s = 0; s < L; s++) {
            const float* src;
            int stride;
            if (t == 0) {
                src = x + (SEQLEN - 1) * IN;   // x[:, -1, :]
                stride = SEQLEN * IN;
            } else {
                int yi = (d == 0) ? s : (L - 1 - s);
                src = g_y + (size_t)yi * BATCH * IN;
                stride = IN;
            }
            cell_round(src, stride, d, b0, j0, Wsm, Asm, bsum, c_reg);
            gridbar(++round);
        }

        // ---- projection: y_t = concat(hF, hB) @ linW^T + linb  (CTAs 0..63)
        // 256 threads: (bsel, half, col); each thread does half of the 512-dot.
        if (ct < 64) {
            int bsel = tid >> 7;           // 0..1
            int half = (tid >> 6) & 1;     // 0..1
            int col  = tid & 63;
            int b = (ct << 1) + bsel;
            const float4* w4 = (const float4*)(linW + col * (2 * HID)) + half * (HID / 4);
            const float4* hv = (const float4*)(g_h + ((half * BATCH) + b) * HID);
            float s = 0.f;
#pragma unroll 8
            for (int q = 0; q < HID / 4; q++) {
                float4 f = __ldcg(hv + q);
                float4 w = __ldg(w4 + q);
                s += f.x * w.x + f.y * w.y + f.z * w.z + f.w * w.w;
            }
            red[tid] = s;
            __syncthreads();
            if (half == 0) {
                float r = red[tid] + red[tid + 64] + linb[col];
                g_y[((size_t)t * BATCH + b) * IN + col] = r;
                out[((size_t)b * PRED + t) * IN + col] = r;
            }
        }
        gridbar(++round);
    }
}

extern "C" void kernel_launch(void* const* d_in, const int* in_sizes, int n_in,
                              void* d_out, int out_size) {
    const float* x    = (const float*)d_in[0];
    const float* eWih = (const float*)d_in[1];
    const float* eWhh = (const float*)d_in[2];
    const float* ebih = (const float*)d_in[3];
    const float* ebhh = (const float*)d_in[4];
    const float* dWih = (const float*)d_in[5];
    const float* dWhh = (const float*)d_in[6];
    const float* dbih = (const float*)d_in[7];
    const float* dbhh = (const float*)d_in[8];
    const float* linW = (const float*)d_in[9];
    const float* linb = (const float*)d_in[10];
    float* out = (float*)d_out;

    // reset barrier flags every launch (captured into the graph -> every replay)
    void* flagsPtr = nullptr;
    cudaGetSymbolAddress(&flagsPtr, g_flags);
    cudaMemsetAsync(flagsPtr, 0, sizeof(int) * NBLK, 0);

    cudaFuncSetAttribute(lstm_s2s_kernel,
                         cudaFuncAttributeMaxDynamicSharedMemorySize, SMEM_BYTES);

    lstm_s2s_kernel<<<NBLK, NTHR, SMEM_BYTES>>>(
        x, eWih, eWhh, ebih, ebhh, dWih, dWhh, dbih, dbhh, linW, linb, out);
}

// round 8
// speedup vs baseline: 1.5936x; 1.5936x over previous
#include <cuda_runtime.h>
#include <cstdint>

// ---------------------------------------------------------------------------
// Seq2seq BiLSTM (encoder 336 steps + autoregressive decoder, 24 iters)
// Persistent cooperative kernel, fp32 FFMA.
//
// Grid = 128 CTAs = 2 dirs x 4 batch-tiles(32) x 16 j-tiles(16), 128 thr/CTA.
// Thread owns 4 batch rows x 4 gates of one hidden unit:
//   - c state in registers for the whole run
//   - W in SMEM, layout [k][jj*4+gate]  -> one LDS.128 yields all 4 gates
//   - h exchanged via L2; *group* barrier over the 16 CTAs sharing (dir,btile)
//     (release-store / acquire-load flag protocol, no membars, hard spin);
//     full 128-CTA barrier only around projections.
// ---------------------------------------------------------------------------

#define NBLK 128
#define NTHR 128

namespace {
constexpr int BATCH = 128;
constexpr int SEQLEN = 336;
constexpr int PRED = 24;
constexpr int IN = 64;
constexpr int HID = 256;
constexpr int KTOT = IN + HID;          // 320
constexpr int WS = 68;                  // W smem row stride (floats), 272B (16B-aligned)
constexpr int AS = 328;                 // A smem row stride (floats), 1312B (16B-aligned)
constexpr int SMEM_FLOATS = KTOT * WS + 32 * AS + 64;
constexpr int SMEM_BYTES = SMEM_FLOATS * 4;   // 129280 B
}

// Persistent device state
__device__ float g_h[2 * BATCH * HID];
__device__ float g_y[PRED * BATCH * IN];
__device__ int   g_flags[NBLK];

__device__ __forceinline__ int ld_acq(const int* p) {
    int v;
    asm volatile("ld.global.acquire.gpu.b32 %0, [%1];" : "=r"(v) : "l"(p) : "memory");
    return v;
}
__device__ __forceinline__ void st_rel(int* p, int v) {
    asm volatile("st.global.release.gpu.b32 [%0], %1;" :: "l"(p), "r"(v) : "memory");
}

__device__ __forceinline__ float fsig(float x) {
    float e = __expf(-x);
    return __fdividef(1.0f, 1.0f + e);
}
__device__ __forceinline__ float ftanh(float x) {
    float ax = fabsf(x);
    float t = __expf(-2.0f * ax);
    float r = __fdividef(1.0f - t, 1.0f + t);
    return copysignf(r, x);
}

// Barrier over g_flags[base .. base+cnt): publish own round, poll the set.
__device__ __forceinline__ void barw(int round, int base, int cnt) {
    __syncthreads();                      // all threads' h-stores issued
    if (threadIdx.x == 0)
        st_rel(&g_flags[blockIdx.x], round);
    if (threadIdx.x < cnt) {
        const int* p = &g_flags[base + threadIdx.x];
        while (ld_acq(p) < round) { }
    }
    __syncthreads();                      // propagate acquire to all threads
}

// W slice -> SMEM: Wsm[k*WS + jj*4 + g], row = g*256 + j0 + jj.
__device__ void load_phase_weights(float* Wsm, float* bsum,
                                   const float* __restrict__ Wih,
                                   const float* __restrict__ Whh,
                                   const float* __restrict__ bih,
                                   const float* __restrict__ bhh,
                                   int d, int j0) {
    for (int idx = threadIdx.x; idx < 64 * KTOT; idx += NTHR) {
        int c = idx / KTOT;
        int k = idx - c * KTOT;
        int jj = c >> 2, g = c & 3;
        int row = g * 256 + j0 + jj;
        float v = (k < IN) ? Wih[(d * 1024 + row) * IN + k]
                           : Whh[(d * 1024 + row) * HID + (k - IN)];
        Wsm[k * WS + c] = v;
    }
    for (int c = threadIdx.x; c < 64; c += NTHR) {
        int jj = c >> 2, g = c & 3;
        int row = g * 256 + j0 + jj;
        bsum[c] = bih[d * 1024 + row] + bhh[d * 1024 + row];
    }
}

// One LSTM cell step for this CTA's slice.
__device__ void cell_round(const float* __restrict__ src, int rowStride,
                           int d, int b0, int j0,
                           const float* Wsm, float* Asm, const float* bsum,
                           float c_reg[4]) {
    const int tid = threadIdx.x;

    // ---- stage A = [x_t | h]: 32 rows x 320 floats (80 float4 per row)
#pragma unroll
    for (int it = 0; it < (32 * 80) / NTHR; it++) {
        int idx = tid + it * NTHR;
        int row = idx / 80;
        int slot = idx - row * 80;
        int b = b0 + row;
        float4 v;
        if (slot < 16)
            v = __ldcg((const float4*)(src + (size_t)b * rowStride) + slot);
        else
            v = __ldcg((const float4*)(g_h + ((d << 7) + b) * HID) + (slot - 16));
        *(float4*)(Asm + row * AS + slot * 4) = v;
    }
    __syncthreads();

    // ---- GEMM: thread = 4 batch rows x 4 gates of hidden unit tj
    const int tj = tid & 15;
    const int tb = tid >> 4;             // 0..7, 4 rows each
    float acc[4][4];
    {
        float4 bv = *(const float4*)(bsum + tj * 4);
#pragma unroll
        for (int bi = 0; bi < 4; bi++) {
            acc[bi][0] = bv.x; acc[bi][1] = bv.y;
            acc[bi][2] = bv.z; acc[bi][3] = bv.w;
        }
    }

    const float* A0 = Asm + (tb * 4 + 0) * AS;
    const float* A1 = A0 + AS;
    const float* A2 = A1 + AS;
    const float* A3 = A2 + AS;
    const float* Wp = Wsm + tj * 4;

#pragma unroll 4
    for (int k = 0; k < KTOT; k += 4) {
        float4 a0 = *(const float4*)(A0 + k);
        float4 a1 = *(const float4*)(A1 + k);
        float4 a2 = *(const float4*)(A2 + k);
        float4 a3 = *(const float4*)(A3 + k);
        float av[4][4] = {{a0.x, a0.y, a0.z, a0.w},
                          {a1.x, a1.y, a1.z, a1.w},
                          {a2.x, a2.y, a2.z, a2.w},
                          {a3.x, a3.y, a3.z, a3.w}};
#pragma unroll
        for (int kk = 0; kk < 4; kk++) {
            float4 w = *(const float4*)(Wp + (k + kk) * WS);
#pragma unroll
            for (int bi = 0; bi < 4; bi++) {
                float a = av[bi][kk];
                acc[bi][0] = fmaf(a, w.x, acc[bi][0]);
                acc[bi][1] = fmaf(a, w.y, acc[bi][1]);
                acc[bi][2] = fmaf(a, w.z, acc[bi][2]);
                acc[bi][3] = fmaf(a, w.w, acc[bi][3]);
            }
        }
    }

    // ---- pointwise LSTM update (c stays in registers), publish h
    int j = j0 + tj;
#pragma unroll
    for (int bi = 0; bi < 4; bi++) {
        int b = b0 + tb * 4 + bi;
        float gi = acc[bi][0], gf = acc[bi][1], gg = acc[bi][2], go = acc[bi][3];
        float cn = fsig(gf) * c_reg[bi] + fsig(gi) * ftanh(gg);
        float hn = fsig(go) * ftanh(cn);
        c_reg[bi] = cn;
        g_h[((d << 7) + b) * HID + j] = hn;
    }
}

__global__ void __launch_bounds__(NTHR, 1)
lstm_s2s_kernel(const float* __restrict__ x,
                const float* __restrict__ eWih, const float* __restrict__ eWhh,
                const float* __restrict__ ebih, const float* __restrict__ ebhh,
                const float* __restrict__ dWih, const float* __restrict__ dWhh,
                const float* __restrict__ dbih, const float* __restrict__ dbhh,
                const float* __restrict__ linW, const float* __restrict__ linb,
                float* __restrict__ out) {
    extern __shared__ float smem[];
    float* Wsm  = smem;                      // [320][68]
    float* Asm  = Wsm + KTOT * WS;           // [32][328]
    float* bsum = Asm + 32 * AS;             // [64]

    const int ct = blockIdx.x;
    const int d = ct >> 6;
    const int rem = ct & 63;
    const int b0 = (rem >> 4) * 32;
    const int j0 = (rem & 15) * 16;
    const int gbase = ct & ~15;              // 16 CTAs sharing (dir, b-tile)
    const int tid = threadIdx.x;

    int round = 0;
    float c_reg[4] = {0.f, 0.f, 0.f, 0.f};

    // zero this CTA's h slice (fresh state every launch/replay)
    for (int idx = tid; idx < 32 * 16; idx += NTHR) {
        int bb = idx >> 4, jj = idx & 15;
        g_h[((d << 7) + b0 + bb) * HID + j0 + jj] = 0.f;
    }

    load_phase_weights(Wsm, bsum, eWih, eWhh, ebih, ebhh, d, j0);
    barw(++round, gbase, 16);

    // ===== encoder: 336 steps, the 8 (dir,b-tile) groups run decoupled =====
    for (int r = 0; r < SEQLEN; r++) {
        int t = (d == 0) ? r : (SEQLEN - 1 - r);
        cell_round(x + t * IN, SEQLEN * IN, d, b0, j0, Wsm, Asm, bsum, c_reg);
        barw(++round, gbase, 16);
    }

    // switch to decoder weights (ordered by the next cell_round's syncthreads)
    load_phase_weights(Wsm, bsum, dWih, dWhh, dbih, dbhh, d, j0);

    // ===== decoder: 24 autoregressive iterations =====
    for (int t = 0; t < PRED; t++) {
        int L = (t == 0) ? 1 : t;
        for (int s = 0; s < L; s++) {
            const float* src;
            int stride;
            if (t == 0) {
                src = x + (SEQLEN - 1) * IN;          // x[:, -1, :]
                stride = SEQLEN * IN;
            } else {
                int yi = (d == 0) ? s : (L - 1 - s);
                src = g_y + (size_t)yi * BATCH * IN;
                stride = IN;
            }
            cell_round(src, stride, d, b0, j0, Wsm, Asm, bsum, c_reg);
            ++round;
            if (s == L - 1) barw(round, 0, NBLK);     // projection reads both dirs
            else            barw(round, gbase, 16);
        }

        // ---- projection: y_t = concat(hF, hB) @ linW^T + linb  (CTAs 0..63)
        if (ct < 64) {
            int b = (ct << 1) + (tid >> 6);           // 2 batch rows per CTA
            int col = tid & 63;
            const float4* w4 = (const float4*)(linW + col * (2 * HID));
            const float4* h0 = (const float4*)(g_h + b * HID);
            const float4* h1 = (const float4*)(g_h + (BATCH + b) * HID);
            float s = linb[col];
#pragma unroll 8
            for (int q = 0; q < HID / 4; q++) {
                float4 f = __ldcg(h0 + q);
                float4 w = __ldg(w4 + q);
                s += f.x * w.x + f.y * w.y + f.z * w.z + f.w * w.w;
            }
#pragma unroll 8
            for (int q = 0; q < HID / 4; q++) {
                float4 f = __ldcg(h1 + q);
                float4 w = __ldg(w4 + HID / 4 + q);
                s += f.x * w.x + f.y * w.y + f.z * w.z + f.w * w.w;
            }
            g_y[((size_t)t * BATCH + b) * IN + col] = s;
            out[((size_t)b * PRED + t) * IN + col] = s;
        }
        barw(++round, 0, NBLK);                       // everyone reads g_y next
    }
}

extern "C" void kernel_launch(void* const* d_in, const int* in_sizes, int n_in,
                              void* d_out, int out_size) {
    const float* x    = (const float*)d_in[0];
    const float* eWih = (const float*)d_in[1];
    const float* eWhh = (const float*)d_in[2];
    const float* ebih = (const float*)d_in[3];
    const float* ebhh = (const float*)d_in[4];
    const float* dWih = (const float*)d_in[5];
    const float* dWhh = (const float*)d_in[6];
    const float* dbih = (const float*)d_in[7];
    const float* dbhh = (const float*)d_in[8];
    const float* linW = (const float*)d_in[9];
    const float* linb = (const float*)d_in[10];
    float* out = (float*)d_out;

    // reset barrier flags every launch (captured -> runs on every replay)
    void* flagsPtr = nullptr;
    cudaGetSymbolAddress(&flagsPtr, g_flags);
    cudaMemsetAsync(flagsPtr, 0, sizeof(int) * NBLK, 0);

    cudaFuncSetAttribute(lstm_s2s_kernel,
                         cudaFuncAttributeMaxDynamicSharedMemorySize, SMEM_BYTES);

    lstm_s2s_kernel<<<NBLK, NTHR, SMEM_BYTES>>>(
        x, eWih, eWhh, ebih, ebhh, dWih, dWhh, dbih, dbhh, linW, linb, out);
}

// round 9
// speedup vs baseline: 2.4719x; 1.5511x over previous
#include <cuda_runtime.h>
#include <cstdint>

// ---------------------------------------------------------------------------
// Seq2seq BiLSTM (encoder 336 steps + autoregressive decoder, 24 iters)
// Persistent cooperative kernel, fp32 FFMA.
//
// Grid = 128 CTAs = 2 dirs x 4 batch-tiles(32) x 16 j-tiles(16), 128 thr/CTA.
// Thread owns 4 batch rows x 4 gates of one hidden unit.
//   - c state in registers for the whole run
//   - W in SMEM, [k][jj*4+gate] -> one LDS.128 = all 4 gate weights
//   - per step: PRE phase (stage x slice + x-part GEMM, k<64) runs BEFORE the
//     flag wait, hiding barrier latency; then h staging + h-part GEMM (k>=64)
//   - group barrier over the 16 CTAs sharing (dir,b-tile); full barrier only
//     around the 24 projections. release-store/acquire-load flags, hard spin.
// ---------------------------------------------------------------------------

#define NBLK 128
#define NTHR 128

namespace {
constexpr int BATCH = 128;
constexpr int SEQLEN = 336;
constexpr int PRED = 24;
constexpr int IN = 64;
constexpr int HID = 256;
constexpr int KTOT = IN + HID;          // 320
constexpr int WS = 68;                  // W smem row stride (floats)
constexpr int AS = 328;                 // A smem row stride (floats)
constexpr int SMEM_FLOATS = KTOT * WS + 32 * AS + 64;
constexpr int SMEM_BYTES = SMEM_FLOATS * 4;   // 129280 B
}

__device__ float g_h[2 * BATCH * HID];
__device__ float g_y[PRED * BATCH * IN];
__device__ int   g_flags[NBLK];

__device__ __forceinline__ int ld_acq(const int* p) {
    int v;
    asm volatile("ld.global.acquire.gpu.b32 %0, [%1];" : "=r"(v) : "l"(p) : "memory");
    return v;
}
__device__ __forceinline__ void st_rel(int* p, int v) {
    asm volatile("st.global.release.gpu.b32 [%0], %1;" :: "l"(p), "r"(v) : "memory");
}

__device__ __forceinline__ float fsig(float x) {
    return __fdividef(1.0f, 1.0f + __expf(-x));
}
__device__ __forceinline__ float ftanh(float x) {
    float ax = fabsf(x);
    float t = __expf(-2.0f * ax);
    float r = __fdividef(1.0f - t, 1.0f + t);
    return copysignf(r, x);
}

// Publish own flag (after CTA-wide sync so all prior stores are ordered by
// the release). Waits are separate so work can be scheduled before them.
__device__ __forceinline__ void release(int v) {
    __syncthreads();
    if (threadIdx.x == 0) st_rel(&g_flags[blockIdx.x], v);
}
__device__ __forceinline__ void waitf(int base, int cnt, int v) {
    if (threadIdx.x < cnt) {
        const int* p = &g_flags[base + threadIdx.x];
        while (ld_acq(p) < v) { }
    }
    __syncthreads();
}

// W slice -> SMEM: Wsm[k*WS + jj*4 + g], source row = g*256 + j0 + jj.
__device__ void load_phase_weights(float* Wsm, float* bsum,
                                   const float* __restrict__ Wih,
                                   const float* __restrict__ Whh,
                                   const float* __restrict__ bih,
                                   const float* __restrict__ bhh,
                                   int d, int j0) {
    for (int idx = threadIdx.x; idx < 64 * KTOT; idx += NTHR) {
        int c = idx / KTOT;
        int k = idx - c * KTOT;
        int jj = c >> 2, g = c & 3;
        int row = g * 256 + j0 + jj;
        float v = (k < IN) ? Wih[(d * 1024 + row) * IN + k]
                           : Whh[(d * 1024 + row) * HID + (k - IN)];
        Wsm[k * WS + c] = v;
    }
    for (int c = threadIdx.x; c < 64; c += NTHR) {
        int jj = c >> 2, g = c & 3;
        int row = g * 256 + j0 + jj;
        bsum[c] = bih[d * 1024 + row] + bhh[d * 1024 + row];
    }
}

// PRE phase: stage x_t tile (32 x 64) and accumulate bias + x-part (k<64).
// No dependency on peers' h -> runs before the flag wait.
__device__ __forceinline__ void cell_pre(const float* __restrict__ src,
                                         int rowStride, int b0,
                                         const float* Wsm, float* Asm,
                                         const float* bsum, float acc[4][4]) {
    const int tid = threadIdx.x;
#pragma unroll
    for (int it = 0; it < 4; it++) {              // 32 rows x 16 float4
        int idx = tid + it * NTHR;
        int row = idx >> 4;
        int slot = idx & 15;
        float4 v = __ldcg((const float4*)(src + (size_t)(b0 + row) * rowStride) + slot);
        *(float4*)(Asm + row * AS + slot * 4) = v;
    }
    __syncthreads();

    const int tj = tid & 15;
    const int tb = tid >> 4;
    {
        float4 bv = *(const float4*)(bsum + tj * 4);
#pragma unroll
        for (int bi = 0; bi < 4; bi++) {
            acc[bi][0] = bv.x; acc[bi][1] = bv.y;
            acc[bi][2] = bv.z; acc[bi][3] = bv.w;
        }
    }
    const float* A0 = Asm + (tb * 4 + 0) * AS;
    const float* A1 = A0 + AS;
    const float* A2 = A1 + AS;
    const float* A3 = A2 + AS;
    const float* Wp = Wsm + tj * 4;

#pragma unroll 2
    for (int k = 0; k < IN; k += 4) {
        float4 a0 = *(const float4*)(A0 + k);
        float4 a1 = *(const float4*)(A1 + k);
        float4 a2 = *(const float4*)(A2 + k);
        float4 a3 = *(const float4*)(A3 + k);
        float av[4][4] = {{a0.x, a0.y, a0.z, a0.w},
                          {a1.x, a1.y, a1.z, a1.w},
                          {a2.x, a2.y, a2.z, a2.w},
                          {a3.x, a3.y, a3.z, a3.w}};
#pragma unroll
        for (int kk = 0; kk < 4; kk++) {
            float4 w = *(const float4*)(Wp + (k + kk) * WS);
#pragma unroll
            for (int bi = 0; bi < 4; bi++) {
                float a = av[bi][kk];
                acc[bi][0] = fmaf(a, w.x, acc[bi][0]);
                acc[bi][1] = fmaf(a, w.y, acc[bi][1]);
                acc[bi][2] = fmaf(a, w.z, acc[bi][2]);
                acc[bi][3] = fmaf(a, w.w, acc[bi][3]);
            }
        }
    }
    // no trailing sync needed: a __syncthreads occurs before Asm x-region is
    // rewritten (h staging sync + next pre's staging barrier).
}

// H phase: stage h tile (32 x 256), h-part GEMM (k=64..319), pointwise, store h.
__device__ __forceinline__ void cell_h(int d, int b0, int j0,
                                       const float* Wsm, float* Asm,
                                       float acc[4][4], float c_reg[4]) {
    const int tid = threadIdx.x;
    // 32 rows x 64 float4, batched MLP=4
#pragma unroll
    for (int it = 0; it < 16; it += 4) {
        float4 v[4];
#pragma unroll
        for (int u = 0; u < 4; u++) {
            int idx = tid + (it + u) * NTHR;
            int row = idx >> 6;
            int slot = idx & 63;
            v[u] = __ldcg((const float4*)(g_h + ((size_t)((d << 7) + b0 + row)) * HID) + slot);
        }
#pragma unroll
        for (int u = 0; u < 4; u++) {
            int idx = tid + (it + u) * NTHR;
            int row = idx >> 6;
            int slot = idx & 63;
            *(float4*)(Asm + row * AS + IN + slot * 4) = v[u];
        }
    }
    __syncthreads();

    const int tj = tid & 15;
    const int tb = tid >> 4;
    const float* A0 = Asm + (tb * 4 + 0) * AS;
    const float* A1 = A0 + AS;
    const float* A2 = A1 + AS;
    const float* A3 = A2 + AS;
    const float* Wp = Wsm + tj * 4;

#pragma unroll 2
    for (int k = IN; k < KTOT; k += 4) {
        float4 a0 = *(const float4*)(A0 + k);
        float4 a1 = *(const float4*)(A1 + k);
        float4 a2 = *(const float4*)(A2 + k);
        float4 a3 = *(const float4*)(A3 + k);
        float av[4][4] = {{a0.x, a0.y, a0.z, a0.w},
                          {a1.x, a1.y, a1.z, a1.w},
                          {a2.x, a2.y, a2.z, a2.w},
                          {a3.x, a3.y, a3.z, a3.w}};
#pragma unroll
        for (int kk = 0; kk < 4; kk++) {
            float4 w = *(const float4*)(Wp + (k + kk) * WS);
#pragma unroll
            for (int bi = 0; bi < 4; bi++) {
                float a = av[bi][kk];
                acc[bi][0] = fmaf(a, w.x, acc[bi][0]);
                acc[bi][1] = fmaf(a, w.y, acc[bi][1]);
                acc[bi][2] = fmaf(a, w.z, acc[bi][2]);
                acc[bi][3] = fmaf(a, w.w, acc[bi][3]);
            }
        }
    }

    int j = j0 + tj;
#pragma unroll
    for (int bi = 0; bi < 4; bi++) {
        int b = b0 + tb * 4 + bi;
        float gi = acc[bi][0], gf = acc[bi][1], gg = acc[bi][2], go = acc[bi][3];
        float cn = fsig(gf) * c_reg[bi] + fsig(gi) * ftanh(gg);
        float hn = fsig(go) * ftanh(cn);
        c_reg[bi] = cn;
        g_h[((size_t)((d << 7) + b)) * HID + j] = hn;
    }
}

__global__ void __launch_bounds__(NTHR, 1)
lstm_s2s_kernel(const float* __restrict__ x,
                const float* __restrict__ eWih, const float* __restrict__ eWhh,
                const float* __restrict__ ebih, const float* __restrict__ ebhh,
                const float* __restrict__ dWih, const float* __restrict__ dWhh,
                const float* __restrict__ dbih, const float* __restrict__ dbhh,
                const float* __restrict__ linW, const float* __restrict__ linb,
                float* __restrict__ out) {
    extern __shared__ float smem[];
    float* Wsm  = smem;                      // [320][68]
    float* Asm  = Wsm + KTOT * WS;           // [32][328]
    float* bsum = Asm + 32 * AS;             // [64]

    const int ct = blockIdx.x;
    const int d = ct >> 6;
    const int rem = ct & 63;
    const int b0 = (rem >> 4) * 32;
    const int j0 = (rem & 15) * 16;
    const int gbase = ct & ~15;              // 16 CTAs sharing (dir, b-tile)
    const int tid = threadIdx.x;

    float c_reg[4] = {0.f, 0.f, 0.f, 0.f};
    float acc[4][4];

    // zero this CTA's h slice (fresh state every replay), publish flag 1
    for (int idx = tid; idx < 32 * 16; idx += NTHR) {
        int bb = idx >> 4, jj = idx & 15;
        g_h[((size_t)((d << 7) + b0 + bb)) * HID + j0 + jj] = 0.f;
    }
    release(1);
    int round = 1;

    load_phase_weights(Wsm, bsum, eWih, eWhh, ebih, ebhh, d, j0);
    // Wsm writes ordered before first GEMM reads by cell_pre's __syncthreads.

    // ===== encoder =====
    for (int r = 0; r < SEQLEN; r++) {
        int t = (d == 0) ? r : (SEQLEN - 1 - r);
        cell_pre(x + t * IN, SEQLEN * IN, b0, Wsm, Asm, bsum, acc);
        waitf(gbase, 16, round);
        cell_h(d, b0, j0, Wsm, Asm, acc, c_reg);
        release(round + 1); round++;
    }

    // ===== switch to decoder weights =====
    load_phase_weights(Wsm, bsum, dWih, dWhh, dbih, dbhh, d, j0);

    // ===== decoder: 24 autoregressive iterations =====
    for (int t = 0; t < PRED; t++) {
        int L = (t == 0) ? 1 : t;
        for (int s = 0; s < L; s++) {
            const float* src;
            int stride;
            if (t == 0) {
                src = x + (SEQLEN - 1) * IN;          // x[:, -1, :]
                stride = SEQLEN * IN;
            } else {
                int yi = (d == 0) ? s : (L - 1 - s);
                src = g_y + (size_t)yi * BATCH * IN;
                stride = IN;
            }
            cell_pre(src, stride, b0, Wsm, Asm, bsum, acc);
            waitf(gbase, 16, round);
            cell_h(d, b0, j0, Wsm, Asm, acc, c_reg);
            release(round + 1); round++;
        }

        // projection needs both dirs' final h
        waitf(0, NBLK, round);
        if (ct < 64) {
            int b = (ct << 1) + (tid >> 6);           // 2 batch rows per CTA
            int col = tid & 63;
            const float4* w4 = (const float4*)(linW + col * (2 * HID));
            const float4* h0 = (const float4*)(g_h + (size_t)b * HID);
            const float4* h1 = (const float4*)(g_h + (size_t)(BATCH + b) * HID);
            float s = linb[col];
#pragma unroll 8
            for (int q = 0; q < HID / 4; q++) {
                float4 f = __ldcg(h0 + q);
                float4 w = __ldg(w4 + q);
                s += f.x * w.x + f.y * w.y + f.z * w.z + f.w * w.w;
            }
#pragma unroll 8
            for (int q = 0; q < HID / 4; q++) {
                float4 f = __ldcg(h1 + q);
                float4 w = __ldg(w4 + HID / 4 + q);
                s += f.x * w.x + f.y * w.y + f.z * w.z + f.w * w.w;
            }
            g_y[((size_t)t * BATCH + b) * IN + col] = s;
            out[((size_t)b * PRED + t) * IN + col] = s;
        }
        release(round + 1); round++;
        waitf(0, NBLK, round);                        // g_y visible before next pre
    }
}

extern "C" void kernel_launch(void* const* d_in, const int* in_sizes, int n_in,
                              void* d_out, int out_size) {
    const float* x    = (const float*)d_in[0];
    const float* eWih = (const float*)d_in[1];
    const float* eWhh = (const float*)d_in[2];
    const float* ebih = (const float*)d_in[3];
    const float* ebhh = (const float*)d_in[4];
    const float* dWih = (const float*)d_in[5];
    const float* dWhh = (const float*)d_in[6];
    const float* dbih = (const float*)d_in[7];
    const float* dbhh = (const float*)d_in[8];
    const float* linW = (const float*)d_in[9];
    const float* linb = (const float*)d_in[10];
    float* out = (float*)d_out;

    void* flagsPtr = nullptr;
    cudaGetSymbolAddress(&flagsPtr, g_flags);
    cudaMemsetAsync(flagsPtr, 0, sizeof(int) * NBLK, 0);

    cudaFuncSetAttribute(lstm_s2s_kernel,
                         cudaFuncAttributeMaxDynamicSharedMemorySize, SMEM_BYTES);

    lstm_s2s_kernel<<<NBLK, NTHR, SMEM_BYTES>>>(
        x, eWih, eWhh, ebih, ebhh, dWih, dWhh, dbih, dbhh, linW, linb, out);
}

// round 10
// speedup vs baseline: 2.5278x; 1.0226x over previous
#include <cuda_runtime.h>
#include <cstdint>

// ---------------------------------------------------------------------------
// Seq2seq BiLSTM (encoder 336 steps + autoregressive decoder, 24 iters)
// Persistent cooperative kernel, packed fp32x2 FFMA2 GEMM.
//
// Grid = 128 CTAs = 2 dirs x 4 batch-tiles(32) x 16 j-tiles(16), 128 thr/CTA.
// Thread owns 4 batch rows x 4 gates of one hidden unit, accumulated as
// gate-pairs in 64-bit packed f32x2 registers:
//   acc[bi][0] = (gate_i, gate_f),  acc[bi][1] = (gate_g, gate_o)
//   weight pair (w_i,w_f) / (w_g,w_o) = one LDS.64 from W smem [k][jj*4+g]
//   activation broadcast pack (a,a) via mov.b64
// Per step: PRE phase (x staging + x-part GEMM) runs before the flag wait
// (hides barrier latency); group barrier over 16 CTAs sharing (dir,b-tile);
// full 128-CTA barrier only around the 24 projections.
// ---------------------------------------------------------------------------

#define NBLK 128
#define NTHR 128

namespace {
constexpr int BATCH = 128;
constexpr int SEQLEN = 336;
constexpr int PRED = 24;
constexpr int IN = 64;
constexpr int HID = 256;
constexpr int KTOT = IN + HID;          // 320
constexpr int WS = 68;                  // W smem row stride (floats), 272B
constexpr int AS = 328;                 // A smem row stride (floats), 1312B
constexpr int SMEM_FLOATS = KTOT * WS + 32 * AS + 64;
constexpr int SMEM_BYTES = SMEM_FLOATS * 4;   // 129280 B
}

__device__ float g_h[2 * BATCH * HID];
__device__ float g_y[PRED * BATCH * IN];
__device__ int   g_flags[NBLK];

using u64 = unsigned long long;

__device__ __forceinline__ int ld_acq(const int* p) {
    int v;
    asm volatile("ld.global.acquire.gpu.b32 %0, [%1];" : "=r"(v) : "l"(p) : "memory");
    return v;
}
__device__ __forceinline__ void st_rel(int* p, int v) {
    asm volatile("st.global.release.gpu.b32 [%0], %1;" :: "l"(p), "r"(v) : "memory");
}

__device__ __forceinline__ u64 ffma2(u64 a, u64 b, u64 c) {
    u64 d;
    asm("fma.rn.f32x2 %0, %1, %2, %3;" : "=l"(d) : "l"(a), "l"(b), "l"(c));
    return d;
}
__device__ __forceinline__ u64 pack2(float lo, float hi) {
    u64 d;
    asm("mov.b64 %0, {%1, %2};" : "=l"(d) : "f"(lo), "f"(hi));
    return d;
}
__device__ __forceinline__ void unpack2(float& lo, float& hi, u64 v) {
    asm("mov.b64 {%0, %1}, %2;" : "=f"(lo), "=f"(hi) : "l"(v));
}

__device__ __forceinline__ float fsig(float x) {
    return __fdividef(1.0f, 1.0f + __expf(-x));
}
__device__ __forceinline__ float ftanh(float x) {
    float ax = fabsf(x);
    float t = __expf(-2.0f * ax);
    float r = __fdividef(1.0f - t, 1.0f + t);
    return copysignf(r, x);
}

// Split barrier: publish own flag after a CTA sync; wait separately so the
// x-part GEMM can be scheduled between release and wait.
__device__ __forceinline__ void release(int v) {
    __syncthreads();
    if (threadIdx.x == 0) st_rel(&g_flags[blockIdx.x], v);
}
__device__ __forceinline__ void waitf(int base, int cnt, int v) {
    if (threadIdx.x < cnt) {
        const int* p = &g_flags[base + threadIdx.x];
        while (ld_acq(p) < v) { }
    }
    __syncthreads();
}

// W slice -> SMEM: Wsm[k*WS + jj*4 + g], source row = g*256 + j0 + jj.
__device__ void load_phase_weights(float* Wsm, float* bsum,
                                   const float* __restrict__ Wih,
                                   const float* __restrict__ Whh,
                                   const float* __restrict__ bih,
                                   const float* __restrict__ bhh,
                                   int d, int j0) {
    for (int idx = threadIdx.x; idx < 64 * KTOT; idx += NTHR) {
        int c = idx / KTOT;
        int k = idx - c * KTOT;
        int jj = c >> 2, g = c & 3;
        int row = g * 256 + j0 + jj;
        float v = (k < IN) ? Wih[(d * 1024 + row) * IN + k]
                           : Whh[(d * 1024 + row) * HID + (k - IN)];
        Wsm[k * WS + c] = v;
    }
    for (int c = threadIdx.x; c < 64; c += NTHR) {
        int jj = c >> 2, g = c & 3;
        int row = g * 256 + j0 + jj;
        bsum[c] = bih[d * 1024 + row] + bhh[d * 1024 + row];
    }
}

// Packed f32x2 GEMM over k range [k0,k1): acc[bi][0]+=(a*wi, a*wf),
// acc[bi][1]+=(a*wg, a*wo).
__device__ __forceinline__ void gemm_span(const float* Asm, const float* Wsm,
                                          int tj, int tb, int k0, int k1,
                                          u64 acc[4][2]) {
    const float* A0 = Asm + (tb * 4 + 0) * AS;
    const float* A1 = A0 + AS;
    const float* A2 = A1 + AS;
    const float* A3 = A2 + AS;

#pragma unroll 2
    for (int k = k0; k < k1; k += 4) {
        float4 a0 = *(const float4*)(A0 + k);
        float4 a1 = *(const float4*)(A1 + k);
        float4 a2 = *(const float4*)(A2 + k);
        float4 a3 = *(const float4*)(A3 + k);
        float av[4][4] = {{a0.x, a0.y, a0.z, a0.w},
                          {a1.x, a1.y, a1.z, a1.w},
                          {a2.x, a2.y, a2.z, a2.w},
                          {a3.x, a3.y, a3.z, a3.w}};
#pragma unroll
        for (int kk = 0; kk < 4; kk++) {
            const u64* Wq = (const u64*)(Wsm + (k + kk) * WS) + tj * 2;
            u64 w01 = Wq[0];          // (w_i, w_f)
            u64 w23 = Wq[1];          // (w_g, w_o)
#pragma unroll
            for (int bi = 0; bi < 4; bi++) {
                u64 ad = pack2(av[bi][kk], av[bi][kk]);
                acc[bi][0] = ffma2(ad, w01, acc[bi][0]);
                acc[bi][1] = ffma2(ad, w23, acc[bi][1]);
            }
        }
    }
}

// PRE phase: stage x_t tile (32 x 64), init bias, x-part GEMM (k<64).
__device__ __forceinline__ void cell_pre(const float* __restrict__ src,
                                         int rowStride, int b0,
                                         const float* Wsm, float* Asm,
                                         const float* bsum, u64 acc[4][2]) {
    const int tid = threadIdx.x;
#pragma unroll
    for (int it = 0; it < 4; it++) {              // 32 rows x 16 float4
        int idx = tid + it * NTHR;
        int row = idx >> 4;
        int slot = idx & 15;
        float4 v = __ldcg((const float4*)(src + (size_t)(b0 + row) * rowStride) + slot);
        *(float4*)(Asm + row * AS + slot * 4) = v;
    }
    __syncthreads();

    const int tj = tid & 15;
    const int tb = tid >> 4;
    {
        float4 bv = *(const float4*)(bsum + tj * 4);
        u64 b01 = pack2(bv.x, bv.y);
        u64 b23 = pack2(bv.z, bv.w);
#pragma unroll
        for (int bi = 0; bi < 4; bi++) { acc[bi][0] = b01; acc[bi][1] = b23; }
    }
    gemm_span(Asm, Wsm, tj, tb, 0, IN, acc);
}

// H phase: stage h tile (32 x 256), h-part GEMM (k=64..319), pointwise.
__device__ __forceinline__ void cell_h(int d, int b0, int j0,
                                       const float* Wsm, float* Asm,
                                       u64 acc[4][2], float c_reg[4]) {
    const int tid = threadIdx.x;
#pragma unroll
    for (int it = 0; it < 16; it += 4) {          // batched MLP=4
        float4 v[4];
#pragma unroll
        for (int u = 0; u < 4; u++) {
            int idx = tid + (it + u) * NTHR;
            int row = idx >> 6;
            int slot = idx & 63;
            v[u] = __ldcg((const float4*)(g_h + ((size_t)((d << 7) + b0 + row)) * HID) + slot);
        }
#pragma unroll
        for (int u = 0; u < 4; u++) {
            int idx = tid + (it + u) * NTHR;
            int row = idx >> 6;
            int slot = idx & 63;
            *(float4*)(Asm + row * AS + IN + slot * 4) = v[u];
        }
    }
    __syncthreads();

    const int tj = tid & 15;
    const int tb = tid >> 4;
    gemm_span(Asm, Wsm, tj, tb, IN, KTOT, acc);

    int j = j0 + tj;
#pragma unroll
    for (int bi = 0; bi < 4; bi++) {
        int b = b0 + tb * 4 + bi;
        float gi, gf, gg, go;
        unpack2(gi, gf, acc[bi][0]);
        unpack2(gg, go, acc[bi][1]);
        float cn = fsig(gf) * c_reg[bi] + fsig(gi) * ftanh(gg);
        float hn = fsig(go) * ftanh(cn);
        c_reg[bi] = cn;
        g_h[((size_t)((d << 7) + b)) * HID + j] = hn;
    }
}

__global__ void __launch_bounds__(NTHR, 1)
lstm_s2s_kernel(const float* __restrict__ x,
                const float* __restrict__ eWih, const float* __restrict__ eWhh,
                const float* __restrict__ ebih, const float* __restrict__ ebhh,
                const float* __restrict__ dWih, const float* __restrict__ dWhh,
                const float* __restrict__ dbih, const float* __restrict__ dbhh,
                const float* __restrict__ linW, const float* __restrict__ linb,
                float* __restrict__ out) {
    extern __shared__ float smem[];
    float* Wsm  = smem;                      // [320][68]
    float* Asm  = Wsm + KTOT * WS;           // [32][328]
    float* bsum = Asm + 32 * AS;             // [64]

    const int ct = blockIdx.x;
    const int d = ct >> 6;
    const int rem = ct & 63;
    const int b0 = (rem >> 4) * 32;
    const int j0 = (rem & 15) * 16;
    const int gbase = ct & ~15;              // 16 CTAs sharing (dir, b-tile)
    const int tid = threadIdx.x;

    float c_reg[4] = {0.f, 0.f, 0.f, 0.f};
    u64 acc[4][2];

    // zero this CTA's h slice (fresh state every replay), publish flag 1
    for (int idx = tid; idx < 32 * 16; idx += NTHR) {
        int bb = idx >> 4, jj = idx & 15;
        g_h[((size_t)((d << 7) + b0 + bb)) * HID + j0 + jj] = 0.f;
    }
    release(1);
    int round = 1;

    load_phase_weights(Wsm, bsum, eWih, eWhh, ebih, ebhh, d, j0);
    // Wsm writes ordered before first GEMM reads by cell_pre's __syncthreads.

    // ===== encoder =====
    for (int r = 0; r < SEQLEN; r++) {
        int t = (d == 0) ? r : (SEQLEN - 1 - r);
        cell_pre(x + t * IN, SEQLEN * IN, b0, Wsm, Asm, bsum, acc);
        waitf(gbase, 16, round);
        cell_h(d, b0, j0, Wsm, Asm, acc, c_reg);
        release(round + 1); round++;
    }

    // ===== switch to decoder weights =====
    load_phase_weights(Wsm, bsum, dWih, dWhh, dbih, dbhh, d, j0);

    // ===== decoder: 24 autoregressive iterations =====
    for (int t = 0; t < PRED; t++) {
        int L = (t == 0) ? 1 : t;
        for (int s = 0; s < L; s++) {
            const float* src;
            int stride;
            if (t == 0) {
                src = x + (SEQLEN - 1) * IN;          // x[:, -1, :]
                stride = SEQLEN * IN;
            } else {
                int yi = (d == 0) ? s : (L - 1 - s);
                src = g_y + (size_t)yi * BATCH * IN;
                stride = IN;
            }
            cell_pre(src, stride, b0, Wsm, Asm, bsum, acc);
            waitf(gbase, 16, round);
            cell_h(d, b0, j0, Wsm, Asm, acc, c_reg);
            release(round + 1); round++;
        }

        // projection needs both dirs' final h
        waitf(0, NBLK, round);
        if (ct < 64) {
            int b = (ct << 1) + (tid >> 6);           // 2 batch rows per CTA
            int col = tid & 63;
            const float4* w4 = (const float4*)(linW + col * (2 * HID));
            const float4* h0 = (const float4*)(g_h + (size_t)b * HID);
            const float4* h1 = (const float4*)(g_h + (size_t)(BATCH + b) * HID);
            float s = linb[col];
#pragma unroll 8
            for (int q = 0; q < HID / 4; q++) {
                float4 f = __ldcg(h0 + q);
                float4 w = __ldg(w4 + q);
                s += f.x * w.x + f.y * w.y + f.z * w.z + f.w * w.w;
            }
#pragma unroll 8
            for (int q = 0; q < HID / 4; q++) {
                float4 f = __ldcg(h1 + q);
                float4 w = __ldg(w4 + HID / 4 + q);
                s += f.x * w.x + f.y * w.y + f.z * w.z + f.w * w.w;
            }
            g_y[((size_t)t * BATCH + b) * IN + col] = s;
            out[((size_t)b * PRED + t) * IN + col] = s;
        }
        release(round + 1); round++;
        waitf(0, NBLK, round);                        // g_y visible before next pre
    }
}

extern "C" void kernel_launch(void* const* d_in, const int* in_sizes, int n_in,
                              void* d_out, int out_size) {
    const float* x    = (const float*)d_in[0];
    const float* eWih = (const float*)d_in[1];
    const float* eWhh = (const float*)d_in[2];
    const float* ebih = (const float*)d_in[3];
    const float* ebhh = (const float*)d_in[4];
    const float* dWih = (const float*)d_in[5];
    const float* dWhh = (const float*)d_in[6];
    const float* dbih = (const float*)d_in[7];
    const float* dbhh = (const float*)d_in[8];
    const float* linW = (const float*)d_in[9];
    const float* linb = (const float*)d_in[10];
    float* out = (float*)d_out;

    void* flagsPtr = nullptr;
    cudaGetSymbolAddress(&flagsPtr, g_flags);
    cudaMemsetAsync(flagsPtr, 0, sizeof(int) * NBLK, 0);

    cudaFuncSetAttribute(lstm_s2s_kernel,
                         cudaFuncAttributeMaxDynamicSharedMemorySize, SMEM_BYTES);

    lstm_s2s_kernel<<<NBLK, NTHR, SMEM_BYTES>>>(
        x, eWih, eWhh, ebih, ebhh, dWih, dWhh, dbih, dbhh, linW, linb, out);
}